// round 4
// baseline (speedup 1.0000x reference)
#include <cuda_runtime.h>

#define NUM_CAMS 6
#define C_FEAT   64
#define HF       16
#define WF       44
#define P_TOTAL  (8 * 128 * 128)                      // 131072
#define FEAT_ELEMS (NUM_CAMS * C_FEAT * HF * WF)      // 270336

// Precomputed per-camera projection (rows 0..2 of cam2img @ ego2cam)
__device__ float g_proj[NUM_CAMS][12];
// NHWC-transposed features: [cam][y][x][c], c contiguous (256B per pixel)
__device__ float g_feat_t[NUM_CAMS * HF * WF * C_FEAT];

// ---------------------------------------------------------------------------
// Prep: transpose (n,c,y,x) -> (n,y,x,c); block 0 also computes projections.
// ---------------------------------------------------------------------------
__global__ void prep_kernel(const float* __restrict__ in,
                            const float* __restrict__ ego2cam,
                            const float* __restrict__ cam2img) {
    int idx = blockIdx.x * blockDim.x + threadIdx.x;
    if (idx < FEAT_ELEMS) {
        int x = idx % WF;
        int t = idx / WF;
        int y = t % HF;  t /= HF;
        int c = t % C_FEAT;
        int n = t / C_FEAT;
        g_feat_t[(((n * HF + y) * WF) + x) * C_FEAT + c] = in[idx];
    }
    if (blockIdx.x == 0 && threadIdx.x < NUM_CAMS * 12) {
        int t = threadIdx.x;
        int n = t / 12;
        int r = (t % 12) / 4;
        int c = t % 4;
        float s = 0.f;
        #pragma unroll
        for (int k = 0; k < 4; k++)
            s += cam2img[n * 16 + r * 4 + k] * ego2cam[n * 16 + k * 4 + c];
        g_proj[n][r * 4 + c] = s;
    }
}

// ---------------------------------------------------------------------------
// Fuse: 16 lanes cooperate per point (channels across lanes -> contiguous
// 256B gathers). Block = 256 threads = 32 points; output staged via smem
// for fully coalesced channel-major stores.
// ---------------------------------------------------------------------------
__global__ void __launch_bounds__(256)
fuse_kernel(const float* __restrict__ vox, float* __restrict__ out) {
    __shared__ float s_out[32][65];        // [point][channel], padded (65: read-side conflict-free)
    __shared__ float s_proj[NUM_CAMS][12];

    int tid = threadIdx.x;
    if (tid < NUM_CAMS * 12)
        s_proj[tid / 12][tid % 12] = g_proj[tid / 12][tid % 12];
    __syncthreads();

    int w    = tid >> 5;        // warp 0..7
    int lane = tid & 31;
    int half = lane >> 4;       // which point of the pair
    int l    = lane & 15;       // channel group 0..15

    int pbase = blockIdx.x * 32;

    #pragma unroll
    for (int it = 0; it < 2; it++) {
        int pt = w * 4 + it * 2 + half;     // 0..31, pair = adjacent x-voxels
        int p  = pbase + pt;

        float px = vox[p];
        float py = vox[P_TOTAL + p];
        float pz = vox[2 * P_TOTAL + p];

        float4 acc = make_float4(0.f, 0.f, 0.f, 0.f);
        int nvalid = 0;

        #pragma unroll
        for (int n = 0; n < NUM_CAMS; n++) {
            const float* M = s_proj[n];
            float uu = M[0] * px + M[1] * py + M[2]  * pz + M[3];
            float vv = M[4] * px + M[5] * py + M[6]  * pz + M[7];
            float dd = M[8] * px + M[9] * py + M[10] * pz + M[11];

            float inv = 1.0f / (dd + 1e-6f);
            float u = uu * inv;
            float v = vv * inv;

            bool valid = (dd > 0.1f) && (u >= 0.f) && (u <= 703.f)
                                     && (v >= 0.f) && (v <= 255.f);
            nvalid += valid ? 1 : 0;

            if (!__any_sync(0xffffffffu, valid)) continue;

            float x = u * (1.0f / 16.0f);
            float y = v * (1.0f / 16.0f);
            float x0f = floorf(x);
            float y0f = floorf(y);
            float wx1 = x - x0f, wy1 = y - y0f;
            float wx0 = 1.f - wx1, wy0 = 1.f - wy1;
            int x0 = (int)x0f;
            int y0 = (int)y0f;

            int dx_off = C_FEAT;
            int dy_off = WF * C_FEAT;
            if (x0 + 1 >= WF) { wx1 = 0.f; dx_off = 0; }
            if (y0 + 1 >= HF) { wy1 = 0.f; dy_off = 0; }

            float w00 = wx0 * wy0;
            float w01 = wx1 * wy0;
            float w10 = wx0 * wy1;
            float w11 = wx1 * wy1;

            int base = ((n * HF + y0) * WF + x0) * C_FEAT;
            if (!valid) {       // dead lane: zero weights, safe address
                w00 = w01 = w10 = w11 = 0.f;
                base = 0; dx_off = 0; dy_off = 0;
            }

            const float* fp = g_feat_t + base + 4 * l;
            float4 a  = *(const float4*)(fp);
            float4 b  = *(const float4*)(fp + dx_off);
            float4 g  = *(const float4*)(fp + dy_off);
            float4 h  = *(const float4*)(fp + dy_off + dx_off);

            acc.x = fmaf(w00, a.x, fmaf(w01, b.x, fmaf(w10, g.x, fmaf(w11, h.x, acc.x))));
            acc.y = fmaf(w00, a.y, fmaf(w01, b.y, fmaf(w10, g.y, fmaf(w11, h.y, acc.y))));
            acc.z = fmaf(w00, a.z, fmaf(w01, b.z, fmaf(w10, g.z, fmaf(w11, h.z, acc.z))));
            acc.w = fmaf(w00, a.w, fmaf(w01, b.w, fmaf(w10, g.w, fmaf(w11, h.w, acc.w))));
        }

        float rden = 1.0f / fmaxf((float)nvalid, 1.0f);
        // Scalar STS: row stride 65 floats is not 16B-aligned for odd pt,
        // so a float4 store here traps (misaligned address).
        s_out[pt][4 * l + 0] = acc.x * rden;
        s_out[pt][4 * l + 1] = acc.y * rden;
        s_out[pt][4 * l + 2] = acc.z * rden;
        s_out[pt][4 * l + 3] = acc.w * rden;
    }

    __syncthreads();

    // Coalesced channel-major writeout: 64 rows x 32 points, 128B per row.
    #pragma unroll
    for (int k = 0; k < 8; k++) {
        int flat = k * 256 + tid;
        int c   = flat >> 5;
        int off = flat & 31;
        out[c * P_TOTAL + pbase + off] = s_out[off][c];
    }
}

// ---------------------------------------------------------------------------
extern "C" void kernel_launch(void* const* d_in, const int* in_sizes, int n_in,
                              void* d_out, int out_size) {
    const float* img_feats = (const float*)d_in[0];   // (6,64,16,44)
    const float* ego2cam   = (const float*)d_in[1];   // (6,4,4)
    const float* cam2img   = (const float*)d_in[2];   // (6,4,4)
    const float* vox       = (const float*)d_in[3];   // (3,8,128,128)
    float* out = (float*)d_out;                       // (1,64,8,128,128)

    prep_kernel<<<(FEAT_ELEMS + 255) / 256, 256>>>(img_feats, ego2cam, cam2img);
    fuse_kernel<<<P_TOTAL / 32, 256>>>(vox, out);
}

// round 6
// speedup vs baseline: 1.5917x; 1.5917x over previous
#include <cuda_runtime.h>

#define NUM_CAMS 6
#define C_FEAT   64
#define HF       16
#define WF       44
#define P_TOTAL  (8 * 128 * 128)                      // 131072
#define FEAT_ELEMS (NUM_CAMS * C_FEAT * HF * WF)      // 270336

#define PTS_PER_BLK 64
#define TASKS (PTS_PER_BLK * NUM_CAMS)                // 384

#define PK_BASE_MASK 0xFFFFF
#define PK_DX_BIT    (1 << 20)
#define PK_DY_BIT    (1 << 21)
#define PK_VALID_BIT (1 << 22)

// Precomputed per-camera projection (rows 0..2 of cam2img @ ego2cam)
__device__ float g_proj[NUM_CAMS][12];
// NHWC-transposed features: [cam][y][x][c], c contiguous (256B per pixel)
__device__ float g_feat_t[NUM_CAMS * HF * WF * C_FEAT];

// ---------------------------------------------------------------------------
// Prep: transpose (n,c,y,x) -> (n,y,x,c); block 0 also computes projections.
// ---------------------------------------------------------------------------
__global__ void prep_kernel(const float* __restrict__ in,
                            const float* __restrict__ ego2cam,
                            const float* __restrict__ cam2img) {
    int idx = blockIdx.x * blockDim.x + threadIdx.x;
    if (idx < FEAT_ELEMS) {
        int x = idx % WF;
        int t = idx / WF;
        int y = t % HF;  t /= HF;
        int c = t % C_FEAT;
        int n = t / C_FEAT;
        g_feat_t[(((n * HF + y) * WF) + x) * C_FEAT + c] = in[idx];
    }
    if (blockIdx.x == 0 && threadIdx.x < NUM_CAMS * 12) {
        int t = threadIdx.x;
        int n = t / 12;
        int r = (t % 12) / 4;
        int c = t % 4;
        float s = 0.f;
        #pragma unroll
        for (int k = 0; k < 4; k++)
            s += cam2img[n * 16 + r * 4 + k] * ego2cam[n * 16 + k * 4 + c];
        g_proj[n][r * 4 + c] = s;
    }
}

// ---------------------------------------------------------------------------
// Fuse, two-stage:
//   Stage 1: each (point,cam) projection computed ONCE (384 tasks / block),
//            weights + packed base + valid count parked in smem. Layout of
//            the task buffers is [cam][pt]  (task = n*64 + pt).
//   Stage 2: 16 lanes per point gather 64 channels (contiguous 256B per
//            corner) and accumulate; smem-staged coalesced writeout.
// ---------------------------------------------------------------------------
__global__ void __launch_bounds__(256)
fuse_kernel(const float* __restrict__ vox, float* __restrict__ out) {
    __shared__ float4 s_w[TASKS];               // 6 KB    [n*64+pt]
    __shared__ int    s_pk[TASKS];              // 1.5 KB  [n*64+pt]
    __shared__ int    s_cnt[PTS_PER_BLK];
    __shared__ float  s_out[PTS_PER_BLK][65];   // 16.25 KB, padded rows

    int tid   = threadIdx.x;
    int pbase = blockIdx.x * PTS_PER_BLK;

    if (tid < PTS_PER_BLK) s_cnt[tid] = 0;
    __syncthreads();

    // ---------------- Stage 1: projections, once per (point, cam) ----------
    for (int task = tid; task < TASKS; task += 256) {
        int pt = task & (PTS_PER_BLK - 1);
        int n  = task >> 6;                      // 0..5   (task = n*64+pt)
        int p  = pbase + pt;

        float px = vox[p];
        float py = vox[P_TOTAL + p];
        float pz = vox[2 * P_TOTAL + p];

        const float* M = g_proj[n];
        float uu = M[0] * px + M[1] * py + M[2]  * pz + M[3];
        float vv = M[4] * px + M[5] * py + M[6]  * pz + M[7];
        float dd = M[8] * px + M[9] * py + M[10] * pz + M[11];

        float inv = 1.0f / (dd + 1e-6f);
        float u = uu * inv;
        float v = vv * inv;

        bool valid = (dd > 0.1f) && (u >= 0.f) && (u <= 703.f)
                                 && (v >= 0.f) && (v <= 255.f);

        float4 w = make_float4(0.f, 0.f, 0.f, 0.f);
        int pk = 0;
        if (valid) {
            float x = u * (1.0f / 16.0f);
            float y = v * (1.0f / 16.0f);
            float x0f = floorf(x);
            float y0f = floorf(y);
            float wx1 = x - x0f, wy1 = y - y0f;
            float wx0 = 1.f - wx1, wy0 = 1.f - wy1;
            int x0 = (int)x0f;
            int y0 = (int)y0f;

            int dxb = PK_DX_BIT, dyb = PK_DY_BIT;
            if (x0 + 1 >= WF) { wx1 = 0.f; dxb = 0; }
            if (y0 + 1 >= HF) { wy1 = 0.f; dyb = 0; }

            w = make_float4(wx0 * wy0, wx1 * wy0, wx0 * wy1, wx1 * wy1);
            int base = ((n * HF + y0) * WF + x0) * C_FEAT;   // < 2^19
            pk = base | dxb | dyb | PK_VALID_BIT;
            atomicAdd(&s_cnt[pt], 1);
        }
        s_w[task]  = w;
        s_pk[task] = pk;
    }
    __syncthreads();

    // ---------------- Stage 2: gather + accumulate --------------------------
    int lane = tid & 31;
    int wrp  = tid >> 5;          // 0..7
    int half = lane >> 4;
    int l    = lane & 15;         // channel group

    #pragma unroll
    for (int it = 0; it < 4; it++) {
        int pt = wrp * 8 + it * 2 + half;   // adjacent x-voxels share cache lines

        float4 acc = make_float4(0.f, 0.f, 0.f, 0.f);

        #pragma unroll
        for (int n = 0; n < NUM_CAMS; n++) {
            int pk = s_pk[n * PTS_PER_BLK + pt];      // [cam][pt] layout
            if (!(pk & PK_VALID_BIT)) continue;

            float4 wg = s_w[n * PTS_PER_BLK + pt];
            int base = pk & PK_BASE_MASK;
            int dx   = (pk & PK_DX_BIT) ? C_FEAT : 0;
            int dy   = (pk & PK_DY_BIT) ? WF * C_FEAT : 0;

            const float* fp = g_feat_t + base + 4 * l;
            float4 a = *(const float4*)(fp);
            float4 b = *(const float4*)(fp + dx);
            float4 g = *(const float4*)(fp + dy);
            float4 h = *(const float4*)(fp + dy + dx);

            acc.x = fmaf(wg.x, a.x, fmaf(wg.y, b.x, fmaf(wg.z, g.x, fmaf(wg.w, h.x, acc.x))));
            acc.y = fmaf(wg.x, a.y, fmaf(wg.y, b.y, fmaf(wg.z, g.y, fmaf(wg.w, h.y, acc.y))));
            acc.z = fmaf(wg.x, a.z, fmaf(wg.y, b.z, fmaf(wg.z, g.z, fmaf(wg.w, h.z, acc.z))));
            acc.w = fmaf(wg.x, a.w, fmaf(wg.y, b.w, fmaf(wg.z, g.w, fmaf(wg.w, h.w, acc.w))));
        }

        float rden = 1.0f / fmaxf((float)s_cnt[pt], 1.0f);
        // scalar STS (row stride 65 floats is not 16B aligned for odd pt)
        s_out[pt][4 * l + 0] = acc.x * rden;
        s_out[pt][4 * l + 1] = acc.y * rden;
        s_out[pt][4 * l + 2] = acc.z * rden;
        s_out[pt][4 * l + 3] = acc.w * rden;
    }

    __syncthreads();

    // ---------------- Coalesced channel-major writeout ----------------------
    // 64 channels x 64 points; each row is a contiguous 256B segment.
    #pragma unroll
    for (int k = 0; k < 16; k++) {
        int flat = k * 256 + tid;
        int c   = flat >> 6;
        int off = flat & 63;
        out[c * P_TOTAL + pbase + off] = s_out[off][c];
    }
}

// ---------------------------------------------------------------------------
extern "C" void kernel_launch(void* const* d_in, const int* in_sizes, int n_in,
                              void* d_out, int out_size) {
    const float* img_feats = (const float*)d_in[0];   // (6,64,16,44)
    const float* ego2cam   = (const float*)d_in[1];   // (6,4,4)
    const float* cam2img   = (const float*)d_in[2];   // (6,4,4)
    const float* vox       = (const float*)d_in[3];   // (3,8,128,128)
    float* out = (float*)d_out;                       // (1,64,8,128,128)

    prep_kernel<<<(FEAT_ELEMS + 255) / 256, 256>>>(img_feats, ego2cam, cam2img);
    fuse_kernel<<<P_TOTAL / PTS_PER_BLK, 256>>>(vox, out);
}

// round 7
// speedup vs baseline: 1.8225x; 1.1450x over previous
#include <cuda_runtime.h>

#define NUM_CAMS 6
#define C_FEAT   64
#define HF       16
#define WF       44
#define P_TOTAL  (8 * 128 * 128)                      // 131072
#define FEAT_ELEMS (NUM_CAMS * C_FEAT * HF * WF)      // 270336

#define PTS_PER_BLK 64
#define TASKS (PTS_PER_BLK * NUM_CAMS)                // 384

// Precomputed per-camera projection (rows 0..2 of cam2img @ ego2cam)
__device__ float g_proj[NUM_CAMS][12];
// NHWC-transposed features: [cam][y][x][c], c contiguous (256B per pixel)
__device__ float g_feat_t[NUM_CAMS * HF * WF * C_FEAT];

// ---------------------------------------------------------------------------
// Prep: transpose (n,c,y,x) -> (n,y,x,c); block 0 also computes projections.
// ---------------------------------------------------------------------------
__global__ void prep_kernel(const float* __restrict__ in,
                            const float* __restrict__ ego2cam,
                            const float* __restrict__ cam2img) {
    int idx = blockIdx.x * blockDim.x + threadIdx.x;
    if (idx < FEAT_ELEMS) {
        int x = idx % WF;
        int t = idx / WF;
        int y = t % HF;  t /= HF;
        int c = t % C_FEAT;
        int n = t / C_FEAT;
        g_feat_t[(((n * HF + y) * WF) + x) * C_FEAT + c] = in[idx];
    }
    if (blockIdx.x == 0 && threadIdx.x < NUM_CAMS * 12) {
        int t = threadIdx.x;
        int n = t / 12;
        int r = (t % 12) / 4;
        int c = t % 4;
        float s = 0.f;
        #pragma unroll
        for (int k = 0; k < 4; k++)
            s += cam2img[n * 16 + r * 4 + k] * ego2cam[n * 16 + k * 4 + c];
        g_proj[n][r * 4 + c] = s;
    }
}

// ---------------------------------------------------------------------------
// Fuse, two-stage with valid-cam bitmask:
//   Stage 1 : each (point,cam) projection once; valid entries write weights
//             (later pre-scaled by 1/cnt) + all four corner offsets (int4);
//             per-point cam bitmask built with atomicOr (order-independent).
//   Scale   : weights *= 1/popc(mask)   (replaces per-point rden tail)
//   Stage 2 : 16 lanes/point, ffs-driven loop over valid cams only; four
//             LDG.128 per cam (contiguous 256B per corner), 16 FFMA.
//   Writeout: smem-staged, STG.128 along points (fully coalesced).
// ---------------------------------------------------------------------------
__global__ void __launch_bounds__(256)
fuse_kernel(const float* __restrict__ vox, float* __restrict__ out) {
    __shared__ float4 s_w[TASKS];               // 6 KB   [n*64+pt]
    __shared__ int4   s_offs[TASKS];            // 6 KB   [n*64+pt]
    __shared__ int    s_mask[PTS_PER_BLK];      // valid-cam bitmask
    __shared__ float  s_out[PTS_PER_BLK][65];   // 16.25 KB, padded rows

    int tid   = threadIdx.x;
    int pbase = blockIdx.x * PTS_PER_BLK;

    if (tid < PTS_PER_BLK) s_mask[tid] = 0;
    __syncthreads();

    // ---------------- Stage 1: projections, once per (point, cam) ----------
    for (int task = tid; task < TASKS; task += 256) {
        int pt = task & (PTS_PER_BLK - 1);
        int n  = task >> 6;                      // 0..5  (task = n*64+pt)
        int p  = pbase + pt;

        float px = vox[p];
        float py = vox[P_TOTAL + p];
        float pz = vox[2 * P_TOTAL + p];

        const float* M = g_proj[n];
        float uu = M[0] * px + M[1] * py + M[2]  * pz + M[3];
        float vv = M[4] * px + M[5] * py + M[6]  * pz + M[7];
        float dd = M[8] * px + M[9] * py + M[10] * pz + M[11];

        float inv = 1.0f / (dd + 1e-6f);
        float u = uu * inv;
        float v = vv * inv;

        bool valid = (dd > 0.1f) && (u >= 0.f) && (u <= 703.f)
                                 && (v >= 0.f) && (v <= 255.f);
        if (valid) {
            float x = u * (1.0f / 16.0f);
            float y = v * (1.0f / 16.0f);
            float x0f = floorf(x);
            float y0f = floorf(y);
            float wx1 = x - x0f, wy1 = y - y0f;
            float wx0 = 1.f - wx1, wy0 = 1.f - wy1;
            int x0 = (int)x0f;
            int y0 = (int)y0f;

            int dx = C_FEAT, dy = WF * C_FEAT;
            if (x0 + 1 >= WF) { wx1 = 0.f; dx = 0; }
            if (y0 + 1 >= HF) { wy1 = 0.f; dy = 0; }

            int base = ((n * HF + y0) * WF + x0) * C_FEAT;
            s_w[task]    = make_float4(wx0 * wy0, wx1 * wy0, wx0 * wy1, wx1 * wy1);
            s_offs[task] = make_int4(base, base + dx, base + dy, base + dy + dx);
            atomicOr(&s_mask[pt], 1 << n);
        }
    }
    __syncthreads();

    // ---------------- Pre-scale weights by 1/cnt ----------------------------
    for (int i = tid; i < TASKS; i += 256) {
        int pt = i & (PTS_PER_BLK - 1);
        int n  = i >> 6;
        int m  = s_mask[pt];
        if ((m >> n) & 1) {
            float r = 1.0f / (float)__popc(m);
            float4 w = s_w[i];
            s_w[i] = make_float4(w.x * r, w.y * r, w.z * r, w.w * r);
        }
    }
    __syncthreads();

    // ---------------- Stage 2: gather + accumulate --------------------------
    int lane = tid & 31;
    int wrp  = tid >> 5;          // 0..7
    int half = lane >> 4;
    int l    = lane & 15;         // channel group
    const float* fB = g_feat_t + 4 * l;

    #pragma unroll
    for (int it = 0; it < 4; it++) {
        int pt = wrp * 8 + it * 2 + half;   // adjacent x-voxels share lines

        float4 acc = make_float4(0.f, 0.f, 0.f, 0.f);

        int m = s_mask[pt];
        while (m) {
            int n = __ffs(m) - 1;
            m &= m - 1;
            int idx = n * PTS_PER_BLK + pt;
            float4 wg = s_w[idx];
            int4   o  = s_offs[idx];

            float4 a = *(const float4*)(fB + o.x);
            float4 b = *(const float4*)(fB + o.y);
            float4 g = *(const float4*)(fB + o.z);
            float4 h = *(const float4*)(fB + o.w);

            acc.x = fmaf(wg.x, a.x, fmaf(wg.y, b.x, fmaf(wg.z, g.x, fmaf(wg.w, h.x, acc.x))));
            acc.y = fmaf(wg.x, a.y, fmaf(wg.y, b.y, fmaf(wg.z, g.y, fmaf(wg.w, h.y, acc.y))));
            acc.z = fmaf(wg.x, a.z, fmaf(wg.y, b.z, fmaf(wg.z, g.z, fmaf(wg.w, h.z, acc.z))));
            acc.w = fmaf(wg.x, a.w, fmaf(wg.y, b.w, fmaf(wg.z, g.w, fmaf(wg.w, h.w, acc.w))));
        }

        // scalar STS (row stride 65 floats: not 16B aligned for odd pt)
        s_out[pt][4 * l + 0] = acc.x;
        s_out[pt][4 * l + 1] = acc.y;
        s_out[pt][4 * l + 2] = acc.z;
        s_out[pt][4 * l + 3] = acc.w;
    }

    __syncthreads();

    // ---------------- Coalesced vectorized writeout -------------------------
    // 64 channels x 64 points; STG.128 along the point dimension.
    #pragma unroll
    for (int k = 0; k < 4; k++) {
        int flat = k * 256 + tid;           // 0..1023 float4 tiles
        int c = flat >> 4;                  // 0..63
        int q = flat & 15;                  // point quad 0..15
        float4 r;
        r.x = s_out[4 * q + 0][c];
        r.y = s_out[4 * q + 1][c];
        r.z = s_out[4 * q + 2][c];
        r.w = s_out[4 * q + 3][c];
        *(float4*)(out + c * P_TOTAL + pbase + 4 * q) = r;
    }
}

// ---------------------------------------------------------------------------
extern "C" void kernel_launch(void* const* d_in, const int* in_sizes, int n_in,
                              void* d_out, int out_size) {
    const float* img_feats = (const float*)d_in[0];   // (6,64,16,44)
    const float* ego2cam   = (const float*)d_in[1];   // (6,4,4)
    const float* cam2img   = (const float*)d_in[2];   // (6,4,4)
    const float* vox       = (const float*)d_in[3];   // (3,8,128,128)
    float* out = (float*)d_out;                       // (1,64,8,128,128)

    prep_kernel<<<(FEAT_ELEMS + 255) / 256, 256>>>(img_feats, ego2cam, cam2img);
    fuse_kernel<<<P_TOTAL / PTS_PER_BLK, 256>>>(vox, out);
}

// round 8
// speedup vs baseline: 1.9078x; 1.0468x over previous
#include <cuda_runtime.h>

#define NUM_CAMS 6
#define C_FEAT   64
#define HF       16
#define WF       44
#define P_TOTAL  (8 * 128 * 128)                      // 131072
#define FEAT_ELEMS (NUM_CAMS * C_FEAT * HF * WF)      // 270336

#define PTS_PER_BLK 64
#define TASKS (PTS_PER_BLK * NUM_CAMS)                // 384

// Precomputed per-camera projection (rows 0..2 of cam2img @ ego2cam)
__device__ float g_proj[NUM_CAMS][12];
// NHWC-transposed features: [cam][y][x][c], c contiguous (256B per pixel)
__device__ float g_feat_t[NUM_CAMS * HF * WF * C_FEAT];

// ---------------------------------------------------------------------------
// Prep: transpose (n,c,y,x) -> (n,y,x,c); block 0 also computes projections.
// ---------------------------------------------------------------------------
__global__ void prep_kernel(const float* __restrict__ in,
                            const float* __restrict__ ego2cam,
                            const float* __restrict__ cam2img) {
    int idx = blockIdx.x * blockDim.x + threadIdx.x;
    if (idx < FEAT_ELEMS) {
        int x = idx % WF;
        int t = idx / WF;
        int y = t % HF;  t /= HF;
        int c = t % C_FEAT;
        int n = t / C_FEAT;
        g_feat_t[(((n * HF + y) * WF) + x) * C_FEAT + c] = in[idx];
    }
    if (blockIdx.x == 0 && threadIdx.x < NUM_CAMS * 12) {
        int t = threadIdx.x;
        int n = t / 12;
        int r = (t % 12) / 4;
        int c = t % 4;
        float s = 0.f;
        #pragma unroll
        for (int k = 0; k < 4; k++)
            s += cam2img[n * 16 + r * 4 + k] * ego2cam[n * 16 + k * 4 + c];
        g_proj[n][r * 4 + c] = s;
    }
}

// ---------------------------------------------------------------------------
// Fuse, two-stage with valid-cam bitmask + chunked writeout (smem diet):
//   Stage 1 : each (point,cam) projection once; valid entries write weights
//             + all four corner offsets (int4); per-point cam bitmask via
//             atomicOr (order-independent -> deterministic).
//   Scale   : weights *= 1/popc(mask)
//   Stage 2 : two chunks of 32 points; 16 lanes/point, ffs loop over valid
//             cams only; 4x LDG.128 per cam (contiguous 256B per corner).
//             s_out is only [32][65] -> total smem ~20.5KB -> 8 blocks/SM.
// ---------------------------------------------------------------------------
__global__ void __launch_bounds__(256)
fuse_kernel(const float* __restrict__ vox, float* __restrict__ out) {
    __shared__ float4 s_w[TASKS];               // 6 KB    [n*64+pt]
    __shared__ int4   s_offs[TASKS];            // 6 KB    [n*64+pt]
    __shared__ int    s_mask[PTS_PER_BLK];      // 256 B
    __shared__ float  s_out[32][65];            // 8.25 KB, padded rows

    int tid   = threadIdx.x;
    int pbase = blockIdx.x * PTS_PER_BLK;

    if (tid < PTS_PER_BLK) s_mask[tid] = 0;
    __syncthreads();

    // ---------------- Stage 1: projections, once per (point, cam) ----------
    for (int task = tid; task < TASKS; task += 256) {
        int pt = task & (PTS_PER_BLK - 1);
        int n  = task >> 6;                      // 0..5  (task = n*64+pt)
        int p  = pbase + pt;

        float px = vox[p];
        float py = vox[P_TOTAL + p];
        float pz = vox[2 * P_TOTAL + p];

        const float* M = g_proj[n];
        float uu = M[0] * px + M[1] * py + M[2]  * pz + M[3];
        float vv = M[4] * px + M[5] * py + M[6]  * pz + M[7];
        float dd = M[8] * px + M[9] * py + M[10] * pz + M[11];

        float inv = 1.0f / (dd + 1e-6f);
        float u = uu * inv;
        float v = vv * inv;

        bool valid = (dd > 0.1f) && (u >= 0.f) && (u <= 703.f)
                                 && (v >= 0.f) && (v <= 255.f);
        if (valid) {
            float x = u * (1.0f / 16.0f);
            float y = v * (1.0f / 16.0f);
            float x0f = floorf(x);
            float y0f = floorf(y);
            float wx1 = x - x0f, wy1 = y - y0f;
            float wx0 = 1.f - wx1, wy0 = 1.f - wy1;
            int x0 = (int)x0f;
            int y0 = (int)y0f;

            int dx = C_FEAT, dy = WF * C_FEAT;
            if (x0 + 1 >= WF) { wx1 = 0.f; dx = 0; }
            if (y0 + 1 >= HF) { wy1 = 0.f; dy = 0; }

            int base = ((n * HF + y0) * WF + x0) * C_FEAT;
            s_w[task]    = make_float4(wx0 * wy0, wx1 * wy0, wx0 * wy1, wx1 * wy1);
            s_offs[task] = make_int4(base, base + dx, base + dy, base + dy + dx);
            atomicOr(&s_mask[pt], 1 << n);
        }
    }
    __syncthreads();

    // ---------------- Pre-scale weights by 1/cnt ----------------------------
    for (int i = tid; i < TASKS; i += 256) {
        int pt = i & (PTS_PER_BLK - 1);
        int n  = i >> 6;
        int m  = s_mask[pt];
        if ((m >> n) & 1) {
            float r = 1.0f / (float)__popc(m);
            float4 w = s_w[i];
            s_w[i] = make_float4(w.x * r, w.y * r, w.z * r, w.w * r);
        }
    }
    __syncthreads();

    // ---------------- Stage 2 + writeout, in 2 chunks of 32 points ----------
    int lane = tid & 31;
    int wrp  = tid >> 5;          // 0..7
    int half = lane >> 4;
    int l    = lane & 15;         // channel group
    const float* fB = g_feat_t + 4 * l;

    #pragma unroll
    for (int chunk = 0; chunk < 2; chunk++) {
        #pragma unroll
        for (int it = 0; it < 2; it++) {
            int pt  = chunk * 32 + wrp * 4 + it * 2 + half;  // global pt
            int row = pt - chunk * 32;                        // s_out row

            float4 acc = make_float4(0.f, 0.f, 0.f, 0.f);

            int m = s_mask[pt];
            while (m) {
                int n = __ffs(m) - 1;
                m &= m - 1;
                int idx = n * PTS_PER_BLK + pt;
                float4 wg = s_w[idx];
                int4   o  = s_offs[idx];

                float4 a = *(const float4*)(fB + o.x);
                float4 b = *(const float4*)(fB + o.y);
                float4 g = *(const float4*)(fB + o.z);
                float4 h = *(const float4*)(fB + o.w);

                acc.x = fmaf(wg.x, a.x, fmaf(wg.y, b.x, fmaf(wg.z, g.x, fmaf(wg.w, h.x, acc.x))));
                acc.y = fmaf(wg.x, a.y, fmaf(wg.y, b.y, fmaf(wg.z, g.y, fmaf(wg.w, h.y, acc.y))));
                acc.z = fmaf(wg.x, a.z, fmaf(wg.y, b.z, fmaf(wg.z, g.z, fmaf(wg.w, h.z, acc.z))));
                acc.w = fmaf(wg.x, a.w, fmaf(wg.y, b.w, fmaf(wg.z, g.w, fmaf(wg.w, h.w, acc.w))));
            }

            // scalar STS (row stride 65 floats: not 16B aligned for odd rows)
            s_out[row][4 * l + 0] = acc.x;
            s_out[row][4 * l + 1] = acc.y;
            s_out[row][4 * l + 2] = acc.z;
            s_out[row][4 * l + 3] = acc.w;
        }

        __syncthreads();

        // Coalesced vectorized writeout of this 32-point chunk:
        // 64 channels x 32 points, STG.128 along the point dimension.
        #pragma unroll
        for (int k = 0; k < 2; k++) {
            int flat = k * 256 + tid;       // 0..511 float4 tiles
            int c = flat >> 3;              // 0..63
            int q = flat & 7;               // point quad 0..7
            float4 r;
            r.x = s_out[4 * q + 0][c];
            r.y = s_out[4 * q + 1][c];
            r.z = s_out[4 * q + 2][c];
            r.w = s_out[4 * q + 3][c];
            *(float4*)(out + c * P_TOTAL + pbase + chunk * 32 + 4 * q) = r;
        }

        __syncthreads();   // protect s_out before next chunk's STS
    }
}

// ---------------------------------------------------------------------------
extern "C" void kernel_launch(void* const* d_in, const int* in_sizes, int n_in,
                              void* d_out, int out_size) {
    const float* img_feats = (const float*)d_in[0];   // (6,64,16,44)
    const float* ego2cam   = (const float*)d_in[1];   // (6,4,4)
    const float* cam2img   = (const float*)d_in[2];   // (6,4,4)
    const float* vox       = (const float*)d_in[3];   // (3,8,128,128)
    float* out = (float*)d_out;                       // (1,64,8,128,128)

    prep_kernel<<<(FEAT_ELEMS + 255) / 256, 256>>>(img_feats, ego2cam, cam2img);
    fuse_kernel<<<P_TOTAL / PTS_PER_BLK, 256>>>(vox, out);
}